// round 5
// baseline (speedup 1.0000x reference)
#include <cuda_runtime.h>
#include <cuda_bf16.h>
#include <math_constants.h>

#define NUM_SEGMENTS 2048
#define EPS 1e-6f
#define F4_PER_ROW 16           // 64 floats per row = 16 float4
#define FUSED_THREADS 1024      // warp cap -> max 2 blocks/SM -> ~37MB L2 set

// ---------------------------------------------------------------------------
// lower_bound over sorted seg: first index i in [0, n) with seg[i] >= key.
// All lanes of a warp run it redundantly (same path -> broadcast loads).
// ---------------------------------------------------------------------------
__device__ __forceinline__ int lower_bound_seg(const int* __restrict__ seg,
                                               int n, int key) {
    int lo = 0, hi = n;
    while (lo < hi) {
        int mid = (lo + hi) >> 1;
        if (__ldg(&seg[mid]) < key) lo = mid + 1;
        else                        hi = mid;
    }
    return lo;
}

// ---------------------------------------------------------------------------
// Single fused kernel: one block per segment.
//  0. Block finds its own row range [r0, r1) by binary search on sorted seg
//     (warp 0 searches r0, warp 1 searches r1 — concurrent, no divergence).
//  1. Pass A: stream rows from DRAM (populate L2), block-reduce min/max.
//  2. Pass B: re-read rows evict-first (L2 hits), FMA, store evict-first.
// No atomics, no helper kernels.
// ---------------------------------------------------------------------------
__global__ __launch_bounds__(FUSED_THREADS)
void mmn_fused_kernel(const float4* __restrict__ x4,
                      const int* __restrict__ seg,
                      float4* __restrict__ out4, int n_rows) {
    __shared__ float s_mn[FUSED_THREADS / 32];
    __shared__ float s_mx[FUSED_THREADS / 32];
    __shared__ int   s_r0, s_r1;
    __shared__ float s_inv, s_b;

    int s    = blockIdx.x;
    int tid  = threadIdx.x;
    int warp = tid >> 5;
    int lane = tid & 31;

    // ---- Find segment bounds ----
    if (warp == 0) {
        int r0 = lower_bound_seg(seg, n_rows, s);
        if (lane == 0) s_r0 = r0;
    } else if (warp == 1) {
        int r1 = lower_bound_seg(seg, n_rows, s + 1);
        if (lane == 0) s_r1 = r1;
    }
    __syncthreads();
    int r0 = s_r0, r1 = s_r1;
    if (r0 >= r1) return;                  // empty segment

    long long f0 = (long long)r0 * F4_PER_ROW;
    long long f1 = (long long)r1 * F4_PER_ROW;

    // ---- Pass A: block min/max over [f0, f1) ----
    float mn = CUDART_INF_F, mx = -CUDART_INF_F;
    #pragma unroll 8
    for (long long i = f0 + tid; i < f1; i += FUSED_THREADS) {
        float4 v = __ldg(&x4[i]);          // populate L2
        mn = fminf(mn, fminf(fminf(v.x, v.y), fminf(v.z, v.w)));
        mx = fmaxf(mx, fmaxf(fmaxf(v.x, v.y), fmaxf(v.z, v.w)));
    }
    #pragma unroll
    for (int m = 16; m >= 1; m >>= 1) {
        mn = fminf(mn, __shfl_xor_sync(0xFFFFFFFFu, mn, m));
        mx = fmaxf(mx, __shfl_xor_sync(0xFFFFFFFFu, mx, m));
    }
    if (lane == 0) { s_mn[warp] = mn; s_mx[warp] = mx; }
    __syncthreads();
    if (warp == 0) {
        const int NW = FUSED_THREADS / 32;
        mn = (lane < NW) ? s_mn[lane] : CUDART_INF_F;
        mx = (lane < NW) ? s_mx[lane] : -CUDART_INF_F;
        #pragma unroll
        for (int m = NW / 2; m >= 1; m >>= 1) {
            mn = fminf(mn, __shfl_xor_sync(0xFFFFFFFFu, mn, m));
            mx = fmaxf(mx, __shfl_xor_sync(0xFFFFFFFFu, mx, m));
        }
        if (lane == 0) {
            float inv = 1.0f / (mx - mn + EPS);
            s_inv = inv;
            s_b   = -mn * inv;
        }
    }
    __syncthreads();
    float inv = s_inv;
    float b   = s_b;

    // ---- Pass B: L2-hit reads (evict after use), evict-first stores ----
    #pragma unroll 4
    for (long long i = f0 + tid; i < f1; i += FUSED_THREADS) {
        float4 v = __ldcs(&x4[i]);         // last use: free the L2 line
        float4 o;
        o.x = fmaf(v.x, inv, b);
        o.y = fmaf(v.y, inv, b);
        o.z = fmaf(v.z, inv, b);
        o.w = fmaf(v.w, inv, b);
        __stcs(&out4[i], o);
    }
}

// ---------------------------------------------------------------------------
extern "C" void kernel_launch(void* const* d_in, const int* in_sizes, int n_in,
                              void* d_out, int out_size) {
    const float* x   = (const float*)d_in[0];
    const int*   seg = (const int*)d_in[1];
    float*       out = (float*)d_out;

    int n_rows = in_sizes[1];   // N

    mmn_fused_kernel<<<NUM_SEGMENTS, FUSED_THREADS>>>(
        (const float4*)x, seg, (float4*)out, n_rows);
}

// round 6
// speedup vs baseline: 1.3315x; 1.3315x over previous
#include <cuda_runtime.h>
#include <cuda_bf16.h>
#include <math_constants.h>

#define NUM_SEGMENTS 2048
#define EPS 1e-6f
#define F4_PER_ROW 16           // 64 floats per row = 16 float4
#define FUSED_THREADS 1024      // warp cap -> max 2 blocks/SM -> ~37MB L2 set

// seg_start[s] = first row of segment s; seg_start[NUM_SEGMENTS] = n_rows
__device__ int g_seg_start[NUM_SEGMENTS + 1];

// ---------------------------------------------------------------------------
// Kernel 1: segment boundaries from sorted seg. int4-vectorized: one thread
// handles 4 consecutive rows, reads its quad once plus one left neighbor.
// For every position where the segment id changes, fill seg_start.
// ---------------------------------------------------------------------------
__global__ void mmn_bounds_kernel(const int4* __restrict__ seg4,
                                  const int* __restrict__ seg, int n_rows) {
    int q = blockIdx.x * blockDim.x + threadIdx.x;   // quad index
    int i0 = q * 4;
    if (i0 >= n_rows) return;

    int4 v = __ldg(&seg4[q]);
    int prev = (i0 == 0) ? -1 : __ldg(&seg[i0 - 1]);

    int vals[5] = {prev, v.x, v.y, v.z, v.w};
    #pragma unroll
    for (int j = 0; j < 4; ++j) {
        int i = i0 + j;
        if (i < n_rows) {
            // fill seg_start[s] = i for all s in (vals[j], vals[j+1]]
            for (int s = vals[j] + 1; s <= vals[j + 1]; ++s)
                g_seg_start[s] = i;
            if (i == n_rows - 1) {
                for (int s = vals[j + 1] + 1; s <= NUM_SEGMENTS; ++s)
                    g_seg_start[s] = n_rows;
            }
        }
    }
}

// ---------------------------------------------------------------------------
// Kernel 2: fused per-segment min/max + normalize (identical to R4 winner).
// One block per segment. Pass A populates L2 + block-reduces min/max;
// Pass B re-reads evict-first (L2 hits), FMA, stores evict-first.
// ---------------------------------------------------------------------------
__global__ __launch_bounds__(FUSED_THREADS)
void mmn_fused_kernel(const float4* __restrict__ x4,
                      float4* __restrict__ out4) {
    __shared__ float s_mn[FUSED_THREADS / 32];
    __shared__ float s_mx[FUSED_THREADS / 32];
    __shared__ float s_inv, s_b;

    int s  = blockIdx.x;
    int r0 = g_seg_start[s];
    int r1 = g_seg_start[s + 1];
    if (r0 >= r1) return;                  // empty segment

    long long f0 = (long long)r0 * F4_PER_ROW;
    long long f1 = (long long)r1 * F4_PER_ROW;
    int tid  = threadIdx.x;
    int warp = tid >> 5;
    int lane = tid & 31;

    // ---- Pass A: block min/max over [f0, f1) ----
    float mn = CUDART_INF_F, mx = -CUDART_INF_F;
    #pragma unroll 4
    for (long long i = f0 + tid; i < f1; i += FUSED_THREADS) {
        float4 v = __ldg(&x4[i]);          // populate L2
        mn = fminf(mn, fminf(fminf(v.x, v.y), fminf(v.z, v.w)));
        mx = fmaxf(mx, fmaxf(fmaxf(v.x, v.y), fmaxf(v.z, v.w)));
    }
    #pragma unroll
    for (int m = 16; m >= 1; m >>= 1) {
        mn = fminf(mn, __shfl_xor_sync(0xFFFFFFFFu, mn, m));
        mx = fmaxf(mx, __shfl_xor_sync(0xFFFFFFFFu, mx, m));
    }
    if (lane == 0) { s_mn[warp] = mn; s_mx[warp] = mx; }
    __syncthreads();
    if (warp == 0) {
        const int NW = FUSED_THREADS / 32;
        mn = (lane < NW) ? s_mn[lane] : CUDART_INF_F;
        mx = (lane < NW) ? s_mx[lane] : -CUDART_INF_F;
        #pragma unroll
        for (int m = NW / 2; m >= 1; m >>= 1) {
            mn = fminf(mn, __shfl_xor_sync(0xFFFFFFFFu, mn, m));
            mx = fmaxf(mx, __shfl_xor_sync(0xFFFFFFFFu, mx, m));
        }
        if (lane == 0) {
            float inv = 1.0f / (mx - mn + EPS);
            s_inv = inv;
            s_b   = -mn * inv;
        }
    }
    __syncthreads();
    float inv = s_inv;
    float b   = s_b;

    // ---- Pass B: L2-hit reads (evict after use), evict-first stores ----
    #pragma unroll 4
    for (long long i = f0 + tid; i < f1; i += FUSED_THREADS) {
        float4 v = __ldcs(&x4[i]);         // last use: free the L2 line
        float4 o;
        o.x = fmaf(v.x, inv, b);
        o.y = fmaf(v.y, inv, b);
        o.z = fmaf(v.z, inv, b);
        o.w = fmaf(v.w, inv, b);
        __stcs(&out4[i], o);
    }
}

// ---------------------------------------------------------------------------
extern "C" void kernel_launch(void* const* d_in, const int* in_sizes, int n_in,
                              void* d_out, int out_size) {
    const float* x   = (const float*)d_in[0];
    const int*   seg = (const int*)d_in[1];
    float*       out = (float*)d_out;

    int n_rows = in_sizes[1];   // N

    // 1. segment boundaries (vectorized)
    int n_quads = (n_rows + 3) / 4;
    mmn_bounds_kernel<<<(n_quads + 255) / 256, 256>>>(
        (const int4*)seg, seg, n_rows);

    // 2. fused min/max + normalize, one block per segment
    mmn_fused_kernel<<<NUM_SEGMENTS, FUSED_THREADS>>>(
        (const float4*)x, (float4*)out);
}